// round 9
// baseline (speedup 1.0000x reference)
#include <cuda_runtime.h>
#include <cstdint>
#include <math_constants.h>

#define BB 64
#define SS 512
#define HH 768
#define LL 9
#define NC 8           // chunks per batch
#define CLEN 64        // steps per chunk

#define NTILES 2048    // 16-row tiles (32768 rows / 16)
#define EGRID  592     // emis grid: 4 blocks/SM on 148 SMs

// Scratch (no allocations allowed) — batch-major chunk outputs
__device__ float g_em[BB * SS * LL];        // raw emissions [B,S,L]
__device__ float g_P[BB * NC * 81];         // [b][c][i*9+j]
__device__ float g_rs[BB * NC * LL];        // [b][c][i]
__device__ float g_np[BB * NC];             // numerator partials
__device__ int   g_mc[BB * NC];             // mask-count partials
__device__ float g_loss[BB];                // per-batch loss
__device__ int   g_done;                    // combine completion counter (self-resetting)

__device__ __forceinline__ float ex2f(float x) {
    float y; asm("ex2.approx.ftz.f32 %0, %1;" : "=f"(y) : "f"(x)); return y;
}
__device__ __forceinline__ float lg2f(float x) {
    float y; asm("lg2.approx.ftz.f32 %0, %1;" : "=f"(y) : "f"(x)); return y;
}

#define L2E 1.4426950408889634f
#define LN2 0.6931471805599453f

// ---------------------------------------------------------------------------
// Kernel 1: emissions = hs @ W + b. Plain FFMA, 2 rows per warp.
// 592 blocks with a grid-stride loop over 16-row tiles: W is staged into
// shared ONCE per block and amortized over ~3.5 tiles (vs 1 tile before).
// ---------------------------------------------------------------------------
__global__ __launch_bounds__(256) void emis_kernel(
    const float* __restrict__ hs, const float* __restrict__ W,
    const float* __restrict__ bias)
{
    __shared__ float shW[LL][HH];
    __shared__ float shb[LL];

    int tid = threadIdx.x;
    for (int idx = tid; idx < LL * HH; idx += 256) {
        int l = idx / HH, h = idx - l * HH;
        shW[l][h] = W[h * LL + l];
    }
    if (tid < LL) shb[tid] = bias[tid];
    __syncthreads();

    int w = tid >> 5, lane = tid & 31;
    const float4* hs4 = (const float4*)hs;

    for (int t = blockIdx.x; t < NTILES; t += EGRID) {
        int row0 = t * 16 + w * 2;

        float acc[2][LL];
#pragma unroll
        for (int r = 0; r < 2; r++)
#pragma unroll
            for (int l = 0; l < LL; l++) acc[r][l] = 0.f;

#pragma unroll
        for (int k = 0; k < 6; k++) {
            int c = lane + 32 * k;
            float4 x0 = hs4[(size_t)row0 * 192 + c];
            float4 x1 = hs4[(size_t)(row0 + 1) * 192 + c];
#pragma unroll
            for (int l = 0; l < LL; l++) {
                float4 wv = ((const float4*)shW[l])[c];
                acc[0][l] += x0.x * wv.x + x0.y * wv.y + x0.z * wv.z + x0.w * wv.w;
                acc[1][l] += x1.x * wv.x + x1.y * wv.y + x1.z * wv.z + x1.w * wv.w;
            }
        }

#pragma unroll
        for (int r = 0; r < 2; r++)
#pragma unroll
            for (int l = 0; l < LL; l++) {
                float v = acc[r][l];
                v += __shfl_xor_sync(0xffffffffu, v, 16);
                v += __shfl_xor_sync(0xffffffffu, v, 8);
                v += __shfl_xor_sync(0xffffffffu, v, 4);
                v += __shfl_xor_sync(0xffffffffu, v, 2);
                v += __shfl_xor_sync(0xffffffffu, v, 1);
                acc[r][l] = v;
            }

#pragma unroll
        for (int r = 0; r < 2; r++) {
            if (lane == r) {
#pragma unroll
                for (int l = 0; l < LL; l++)
                    g_em[(size_t)(row0 + r) * LL + l] = acc[r][l] + shb[l];
            }
        }
    }
}

// ---------------------------------------------------------------------------
// Kernel 2: chunked scan + fused numerator partials. Grid (NC, BB), 128 thr.
// Warps 0-2: 9x9 transfer matrix of a 64-step chunk (3 rows per warp).
// Warp 3: gold-path numerator partial + mask count for the chunk.
// exp2 of emissions computed on the fly while staging into smem.
// ---------------------------------------------------------------------------
__global__ __launch_bounds__(128) void crf_chunk_kernel(
    const int* __restrict__ mask, const int* __restrict__ labels,
    const float* __restrict__ trans, const float* __restrict__ start_t)
{
    __shared__ float sem[CLEN * LL];
    __shared__ int smk[CLEN];
    __shared__ int slb[CLEN];

    int c = blockIdx.x;
    int b = blockIdx.y;
    int tid = threadIdx.x;
    int warp = tid >> 5, lane = tid & 31;
    int t0 = c * CLEN;

    for (int i = tid; i < CLEN * LL; i += 128)
        sem[i] = ex2f(g_em[((size_t)b * SS + t0) * LL + i] * L2E);
    if (tid < CLEN) smk[tid] = mask[b * SS + t0 + tid];
    else if (tid < 2 * CLEN) slb[tid - CLEN] = labels[b * SS + t0 + tid - CLEN];
    __syncthreads();

    if (warp < 3) {
        int lr = lane / 9, j = lane - lr * 9;   // lanes 27-31: harmless garbage
        int row = warp * 3 + lr;

        float et[LL];
#pragma unroll
        for (int i = 0; i < LL; i++)
            et[i] = ex2f(trans[i * LL + j] * L2E);

        int base = lr * 9;
        float a = (row == j) ? 1.f : 0.f;
        float rs = 0.f;

        int s0 = (c == 0) ? 1 : 0;
#pragma unroll 8
        for (int s = s0; s < CLEN; s++) {
            float em = sem[s * LL + j];
            int   m  = smk[s];
            float v0 = 0.f, v1 = 0.f, v2 = 0.f;
#pragma unroll
            for (int i = 0; i < 9; i += 3) {
                v0 += __shfl_sync(0xffffffffu, a, base + i)     * et[i];
                v1 += __shfl_sync(0xffffffffu, a, base + i + 1) * et[i + 1];
                v2 += __shfl_sync(0xffffffffu, a, base + i + 2) * et[i + 2];
            }
            float v = (v0 + v1 + v2) * em;
            a = m ? v : a;

            if ((s & 7) == 7) {
                float mx = -CUDART_INF_F;
#pragma unroll
                for (int i = 0; i < 9; i++)
                    mx = fmaxf(mx, __shfl_sync(0xffffffffu, a, base + i));
                a *= (1.f / mx);
                rs += lg2f(mx);
            }
        }

        if (lane < 27) {
            g_P[((size_t)b * NC + c) * 81 + row * 9 + j] = a;
            if (j == 0)
                g_rs[((size_t)b * NC + c) * LL + row] = rs;
        }
    } else {
        // numerator partial: 2 steps per lane
        float acc = 0.f;
        int mc = 0;
#pragma unroll
        for (int ss = lane; ss < CLEN; ss += 32) {
            int l = slb[ss];
            int m = smk[ss];
            mc += m;
            float em = g_em[((size_t)b * SS + t0 + ss) * LL + l];
            if (c == 0 && ss == 0) {
                acc += start_t[l] + em;          // unmasked first term
            } else {
                int lprev = (ss == 0) ? labels[b * SS + t0 - 1] : slb[ss - 1];
                acc += m ? (__ldg(&trans[lprev * LL + l]) + em) : 0.f;
            }
        }
#pragma unroll
        for (int off = 16; off > 0; off >>= 1) {
            acc += __shfl_xor_sync(0xffffffffu, acc, off);
            mc  += __shfl_xor_sync(0xffffffffu, mc,  off);
        }
        if (lane == 0) {
            g_np[b * NC + c] = acc;
            g_mc[b * NC + c] = mc;
        }
    }
}

// ---------------------------------------------------------------------------
// Kernel 3: combine — one block (1 warp) per batch. Stage chunk data into
// smem coalesced, fold from smem, then the LAST block to finish performs the
// deterministic 64-way final sum (threadfence-reduction pattern).
// ---------------------------------------------------------------------------
__global__ __launch_bounds__(32) void crf_combine_kernel(
    const float* __restrict__ start_t, const float* __restrict__ end_t,
    const int* __restrict__ labels, float* __restrict__ out)
{
    __shared__ float sP[NC * 81];
    __shared__ float srs[NC * LL];
    __shared__ float salpha[LL];
    __shared__ float sv[LL];

    int b = blockIdx.x;
    int lane = threadIdx.x;

    // coalesced stage (full-warp MLP)
    for (int i = lane; i < NC * 81; i += 32)
        sP[i] = g_P[(size_t)b * NC * 81 + i];
    for (int i = lane; i < NC * LL; i += 32)
        srs[i] = g_rs[(size_t)b * NC * LL + i];
    if (lane < LL)
        salpha[lane] = ex2f((start_t[lane] + g_em[(size_t)b * SS * LL + lane]) * L2E);
    __syncwarp();

    float sc = 0.f;
#pragma unroll
    for (int c = 0; c < NC; c++) {
        float rmax = srs[c * LL];
#pragma unroll
        for (int i = 1; i < LL; i++) rmax = fmaxf(rmax, srs[c * LL + i]);

        float ai[LL];
#pragma unroll
        for (int i = 0; i < LL; i++)
            ai[i] = salpha[i] * ex2f(srs[c * LL + i] - rmax);

        if (lane < LL) {
            float v = 0.f;
#pragma unroll
            for (int i = 0; i < LL; i++)
                v += ai[i] * sP[c * 81 + i * 9 + lane];
            sv[lane] = v;
        }
        __syncwarp();

        float mx = sv[0];
#pragma unroll
        for (int j = 1; j < LL; j++) mx = fmaxf(mx, sv[j]);

        if (lane < LL) salpha[lane] = sv[lane] * (1.f / mx);
        sc += rmax + lg2f(mx);
        __syncwarp();
    }

    // denom (every lane computes the same value; lane 0 writes)
    float ssum = 0.f;
#pragma unroll
    for (int j = 0; j < LL; j++)
        ssum += salpha[j] * ex2f(end_t[j] * L2E);
    float denom = (sc + lg2f(ssum)) * LN2;

    int isLast = 0;
    if (lane == 0) {
        float num = 0.f;
        int mt = 0;
#pragma unroll
        for (int c = 0; c < NC; c++) {
            num += g_np[b * NC + c];
            mt  += g_mc[b * NC + c];
        }
        num += end_t[labels[b * SS + mt - 1]];
        g_loss[b] = denom - num;
        __threadfence();
        int v = atomicAdd(&g_done, 1);
        isLast = (v == BB - 1);
    }
    isLast = __shfl_sync(0xffffffffu, isLast, 0);

    if (isLast) {
        __threadfence();     // acquire: make all g_loss writes visible
        float v = g_loss[lane] + g_loss[lane + 32];
        v += __shfl_xor_sync(0xffffffffu, v, 16);
        v += __shfl_xor_sync(0xffffffffu, v, 8);
        v += __shfl_xor_sync(0xffffffffu, v, 4);
        v += __shfl_xor_sync(0xffffffffu, v, 2);
        v += __shfl_xor_sync(0xffffffffu, v, 1);
        if (lane == 0) {
            out[0] = v;
            g_done = 0;      // reset for next graph replay
        }
    }
}

// ---------------------------------------------------------------------------
extern "C" void kernel_launch(void* const* d_in, const int* in_sizes, int n_in,
                              void* d_out, int out_size)
{
    const float* hs      = (const float*)d_in[0];
    const int*   mask    = (const int*)  d_in[1];
    const int*   labels  = (const int*)  d_in[2];
    const float* W       = (const float*)d_in[3];
    const float* bias    = (const float*)d_in[4];
    const float* start_t = (const float*)d_in[5];
    const float* end_t   = (const float*)d_in[6];
    const float* trans   = (const float*)d_in[7];
    float* out = (float*)d_out;

    emis_kernel<<<EGRID, 256>>>(hs, W, bias);
    crf_chunk_kernel<<<dim3(NC, BB), 128>>>(mask, labels, trans, start_t);
    crf_combine_kernel<<<BB, 32>>>(start_t, end_t, labels, out);
}

// round 10
// speedup vs baseline: 1.0635x; 1.0635x over previous
#include <cuda_runtime.h>
#include <cstdint>
#include <math_constants.h>

#define BB 64
#define SS 512
#define HH 768
#define LL 9
#define NC 8           // chunks per batch
#define CLEN 64        // steps per chunk

#define TILES_PER_BLOCK 4
#define EGRID 512      // 512 blocks x 4 tiles x 16 rows = 32768 rows

// Scratch (no allocations allowed) — batch-major chunk outputs
__device__ float g_em[BB * SS * LL];        // raw emissions [B,S,L]
__device__ float g_P[BB * NC * 81];         // [b][c][i*9+j]
__device__ float g_rs[BB * NC * LL];        // [b][c][i]
__device__ float g_np[BB * NC];             // numerator partials
__device__ int   g_mc[BB * NC];             // mask-count partials
__device__ float g_loss[BB];                // per-batch loss
__device__ int   g_done;                    // combine completion counter (self-resetting)

__device__ __forceinline__ float ex2f(float x) {
    float y; asm("ex2.approx.ftz.f32 %0, %1;" : "=f"(y) : "f"(x)); return y;
}
__device__ __forceinline__ float lg2f(float x) {
    float y; asm("lg2.approx.ftz.f32 %0, %1;" : "=f"(y) : "f"(x)); return y;
}

#define L2E 1.4426950408889634f
#define LN2 0.6931471805599453f

// ---------------------------------------------------------------------------
// Kernel 1: emissions = hs @ W + b. Plain FFMA, 2 rows per warp.
// 512 blocks, each handling 4 consecutive 16-row tiles with a strictly
// NON-UNROLLED outer loop (prevents the R9 register explosion) so the W
// shared-stage is amortized 4x.
// ---------------------------------------------------------------------------
__global__ __launch_bounds__(256) void emis_kernel(
    const float* __restrict__ hs, const float* __restrict__ W,
    const float* __restrict__ bias)
{
    __shared__ float shW[LL][HH];
    __shared__ float shb[LL];

    int tid = threadIdx.x;
    for (int idx = tid; idx < LL * HH; idx += 256) {
        int l = idx / HH, h = idx - l * HH;
        shW[l][h] = W[h * LL + l];
    }
    if (tid < LL) shb[tid] = bias[tid];
    __syncthreads();

    int w = tid >> 5, lane = tid & 31;
    const float4* hs4 = (const float4*)hs;

#pragma unroll 1
    for (int it = 0; it < TILES_PER_BLOCK; it++) {
        int row0 = (blockIdx.x * TILES_PER_BLOCK + it) * 16 + w * 2;

        float acc[2][LL];
#pragma unroll
        for (int r = 0; r < 2; r++)
#pragma unroll
            for (int l = 0; l < LL; l++) acc[r][l] = 0.f;

#pragma unroll
        for (int k = 0; k < 6; k++) {
            int c = lane + 32 * k;
            float4 x0 = hs4[(size_t)row0 * 192 + c];
            float4 x1 = hs4[(size_t)(row0 + 1) * 192 + c];
#pragma unroll
            for (int l = 0; l < LL; l++) {
                float4 wv = ((const float4*)shW[l])[c];
                acc[0][l] += x0.x * wv.x + x0.y * wv.y + x0.z * wv.z + x0.w * wv.w;
                acc[1][l] += x1.x * wv.x + x1.y * wv.y + x1.z * wv.z + x1.w * wv.w;
            }
        }

#pragma unroll
        for (int r = 0; r < 2; r++)
#pragma unroll
            for (int l = 0; l < LL; l++) {
                float v = acc[r][l];
                v += __shfl_xor_sync(0xffffffffu, v, 16);
                v += __shfl_xor_sync(0xffffffffu, v, 8);
                v += __shfl_xor_sync(0xffffffffu, v, 4);
                v += __shfl_xor_sync(0xffffffffu, v, 2);
                v += __shfl_xor_sync(0xffffffffu, v, 1);
                acc[r][l] = v;
            }

#pragma unroll
        for (int r = 0; r < 2; r++) {
            if (lane == r) {
#pragma unroll
                for (int l = 0; l < LL; l++)
                    g_em[(size_t)(row0 + r) * LL + l] = acc[r][l] + shb[l];
            }
        }
    }
}

// ---------------------------------------------------------------------------
// Kernel 2: chunked scan + fused numerator partials. Grid (NC, BB), 128 thr.
// Warps 0-2: 9x9 transfer matrix of a 64-step chunk (3 rows per warp).
// Warp 3: gold-path numerator partial + mask count for the chunk.
// exp2 of emissions computed on the fly while staging into smem.
// ---------------------------------------------------------------------------
__global__ __launch_bounds__(128) void crf_chunk_kernel(
    const int* __restrict__ mask, const int* __restrict__ labels,
    const float* __restrict__ trans, const float* __restrict__ start_t)
{
    __shared__ float sem[CLEN * LL];
    __shared__ int smk[CLEN];
    __shared__ int slb[CLEN];

    int c = blockIdx.x;
    int b = blockIdx.y;
    int tid = threadIdx.x;
    int warp = tid >> 5, lane = tid & 31;
    int t0 = c * CLEN;

    for (int i = tid; i < CLEN * LL; i += 128)
        sem[i] = ex2f(g_em[((size_t)b * SS + t0) * LL + i] * L2E);
    if (tid < CLEN) smk[tid] = mask[b * SS + t0 + tid];
    else if (tid < 2 * CLEN) slb[tid - CLEN] = labels[b * SS + t0 + tid - CLEN];
    __syncthreads();

    if (warp < 3) {
        int lr = lane / 9, j = lane - lr * 9;   // lanes 27-31: harmless garbage
        int row = warp * 3 + lr;

        float et[LL];
#pragma unroll
        for (int i = 0; i < LL; i++)
            et[i] = ex2f(trans[i * LL + j] * L2E);

        int base = lr * 9;
        float a = (row == j) ? 1.f : 0.f;
        float rs = 0.f;

        int s0 = (c == 0) ? 1 : 0;
#pragma unroll 8
        for (int s = s0; s < CLEN; s++) {
            float em = sem[s * LL + j];
            int   m  = smk[s];
            float v0 = 0.f, v1 = 0.f, v2 = 0.f;
#pragma unroll
            for (int i = 0; i < 9; i += 3) {
                v0 += __shfl_sync(0xffffffffu, a, base + i)     * et[i];
                v1 += __shfl_sync(0xffffffffu, a, base + i + 1) * et[i + 1];
                v2 += __shfl_sync(0xffffffffu, a, base + i + 2) * et[i + 2];
            }
            float v = (v0 + v1 + v2) * em;
            a = m ? v : a;

            if ((s & 7) == 7) {
                float mx = -CUDART_INF_F;
#pragma unroll
                for (int i = 0; i < 9; i++)
                    mx = fmaxf(mx, __shfl_sync(0xffffffffu, a, base + i));
                a *= (1.f / mx);
                rs += lg2f(mx);
            }
        }

        if (lane < 27) {
            g_P[((size_t)b * NC + c) * 81 + row * 9 + j] = a;
            if (j == 0)
                g_rs[((size_t)b * NC + c) * LL + row] = rs;
        }
    } else {
        // numerator partial: 2 steps per lane
        float acc = 0.f;
        int mc = 0;
#pragma unroll
        for (int ss = lane; ss < CLEN; ss += 32) {
            int l = slb[ss];
            int m = smk[ss];
            mc += m;
            float em = g_em[((size_t)b * SS + t0 + ss) * LL + l];
            if (c == 0 && ss == 0) {
                acc += start_t[l] + em;          // unmasked first term
            } else {
                int lprev = (ss == 0) ? labels[b * SS + t0 - 1] : slb[ss - 1];
                acc += m ? (__ldg(&trans[lprev * LL + l]) + em) : 0.f;
            }
        }
#pragma unroll
        for (int off = 16; off > 0; off >>= 1) {
            acc += __shfl_xor_sync(0xffffffffu, acc, off);
            mc  += __shfl_xor_sync(0xffffffffu, mc,  off);
        }
        if (lane == 0) {
            g_np[b * NC + c] = acc;
            g_mc[b * NC + c] = mc;
        }
    }
}

// ---------------------------------------------------------------------------
// Kernel 3: combine — one block (1 warp) per batch. Stage chunk data into
// smem coalesced, fold from smem, then the LAST block to finish performs the
// deterministic 64-way final sum (threadfence-reduction pattern).
// ---------------------------------------------------------------------------
__global__ __launch_bounds__(32) void crf_combine_kernel(
    const float* __restrict__ start_t, const float* __restrict__ end_t,
    const int* __restrict__ labels, float* __restrict__ out)
{
    __shared__ float sP[NC * 81];
    __shared__ float srs[NC * LL];
    __shared__ float salpha[LL];
    __shared__ float sv[LL];

    int b = blockIdx.x;
    int lane = threadIdx.x;

    // coalesced stage (full-warp MLP)
    for (int i = lane; i < NC * 81; i += 32)
        sP[i] = g_P[(size_t)b * NC * 81 + i];
    for (int i = lane; i < NC * LL; i += 32)
        srs[i] = g_rs[(size_t)b * NC * LL + i];
    if (lane < LL)
        salpha[lane] = ex2f((start_t[lane] + g_em[(size_t)b * SS * LL + lane]) * L2E);
    __syncwarp();

    float sc = 0.f;
#pragma unroll
    for (int c = 0; c < NC; c++) {
        float rmax = srs[c * LL];
#pragma unroll
        for (int i = 1; i < LL; i++) rmax = fmaxf(rmax, srs[c * LL + i]);

        float ai[LL];
#pragma unroll
        for (int i = 0; i < LL; i++)
            ai[i] = salpha[i] * ex2f(srs[c * LL + i] - rmax);

        if (lane < LL) {
            float v = 0.f;
#pragma unroll
            for (int i = 0; i < LL; i++)
                v += ai[i] * sP[c * 81 + i * 9 + lane];
            sv[lane] = v;
        }
        __syncwarp();

        float mx = sv[0];
#pragma unroll
        for (int j = 1; j < LL; j++) mx = fmaxf(mx, sv[j]);

        if (lane < LL) salpha[lane] = sv[lane] * (1.f / mx);
        sc += rmax + lg2f(mx);
        __syncwarp();
    }

    // denom (every lane computes the same value; lane 0 writes)
    float ssum = 0.f;
#pragma unroll
    for (int j = 0; j < LL; j++)
        ssum += salpha[j] * ex2f(end_t[j] * L2E);
    float denom = (sc + lg2f(ssum)) * LN2;

    int isLast = 0;
    if (lane == 0) {
        float num = 0.f;
        int mt = 0;
#pragma unroll
        for (int c = 0; c < NC; c++) {
            num += g_np[b * NC + c];
            mt  += g_mc[b * NC + c];
        }
        num += end_t[labels[b * SS + mt - 1]];
        g_loss[b] = denom - num;
        __threadfence();
        int v = atomicAdd(&g_done, 1);
        isLast = (v == BB - 1);
    }
    isLast = __shfl_sync(0xffffffffu, isLast, 0);

    if (isLast) {
        __threadfence();     // acquire: make all g_loss writes visible
        float v = g_loss[lane] + g_loss[lane + 32];
        v += __shfl_xor_sync(0xffffffffu, v, 16);
        v += __shfl_xor_sync(0xffffffffu, v, 8);
        v += __shfl_xor_sync(0xffffffffu, v, 4);
        v += __shfl_xor_sync(0xffffffffu, v, 2);
        v += __shfl_xor_sync(0xffffffffu, v, 1);
        if (lane == 0) {
            out[0] = v;
            g_done = 0;      // reset for next graph replay
        }
    }
}

// ---------------------------------------------------------------------------
extern "C" void kernel_launch(void* const* d_in, const int* in_sizes, int n_in,
                              void* d_out, int out_size)
{
    const float* hs      = (const float*)d_in[0];
    const int*   mask    = (const int*)  d_in[1];
    const int*   labels  = (const int*)  d_in[2];
    const float* W       = (const float*)d_in[3];
    const float* bias    = (const float*)d_in[4];
    const float* start_t = (const float*)d_in[5];
    const float* end_t   = (const float*)d_in[6];
    const float* trans   = (const float*)d_in[7];
    float* out = (float*)d_out;

    emis_kernel<<<EGRID, 256>>>(hs, W, bias);
    crf_chunk_kernel<<<dim3(NC, BB), 128>>>(mask, labels, trans, start_t);
    crf_combine_kernel<<<BB, 32>>>(start_t, end_t, labels, out);
}

// round 11
// speedup vs baseline: 1.7857x; 1.6791x over previous
#include <cuda_runtime.h>
#include <cstdint>
#include <math_constants.h>

#define BB 64
#define SS 512
#define HH 768
#define LL 9
#define NC 8           // chunks per batch
#define CLEN 64        // steps per chunk

#define EGRID 1024     // 1024 blocks x 16 warps x 2 rows = 32768 rows

// Scratch (no allocations allowed) — batch-major chunk outputs
__device__ float g_em[BB * SS * LL];        // raw emissions [B,S,L]
__device__ float g_P[BB * NC * 81];         // [b][c][i*9+j]
__device__ float g_rs[BB * NC * LL];        // [b][c][i]
__device__ float g_np[BB * NC];             // numerator partials
__device__ int   g_mc[BB * NC];             // mask-count partials
__device__ float g_loss[BB];                // per-batch loss
__device__ int   g_done;                    // combine completion counter (self-resetting)

__device__ __forceinline__ float ex2f(float x) {
    float y; asm("ex2.approx.ftz.f32 %0, %1;" : "=f"(y) : "f"(x)); return y;
}
__device__ __forceinline__ float lg2f(float x) {
    float y; asm("lg2.approx.ftz.f32 %0, %1;" : "=f"(y) : "f"(x)); return y;
}

#define L2E 1.4426950408889634f
#define LN2 0.6931471805599453f

// ---------------------------------------------------------------------------
// Kernel 1: emissions = hs @ W + b. Plain FFMA, 2 rows per warp, FLAT body
// (no tile loop — ptxas pipelines any rolled loop into a 255-reg monster).
// 512 threads/block halves W-staging work vs 256 and doubles stage
// amortization; 59 regs -> 2 blocks/SM -> 50% occupancy.
// ---------------------------------------------------------------------------
__global__ __launch_bounds__(512) void emis_kernel(
    const float* __restrict__ hs, const float* __restrict__ W,
    const float* __restrict__ bias)
{
    __shared__ float shW[LL][HH];
    __shared__ float shb[LL];

    int tid = threadIdx.x;
    for (int idx = tid; idx < LL * HH; idx += 512) {
        int l = idx / HH, h = idx - l * HH;
        shW[l][h] = W[h * LL + l];
    }
    if (tid < LL) shb[tid] = bias[tid];
    __syncthreads();

    int w = tid >> 5, lane = tid & 31;
    int row0 = (blockIdx.x * 16 + w) * 2;
    const float4* hs4 = (const float4*)hs;

    float acc[2][LL];
#pragma unroll
    for (int r = 0; r < 2; r++)
#pragma unroll
        for (int l = 0; l < LL; l++) acc[r][l] = 0.f;

#pragma unroll
    for (int k = 0; k < 6; k++) {
        int c = lane + 32 * k;
        float4 x0 = hs4[(size_t)row0 * 192 + c];
        float4 x1 = hs4[(size_t)(row0 + 1) * 192 + c];
#pragma unroll
        for (int l = 0; l < LL; l++) {
            float4 wv = ((const float4*)shW[l])[c];
            acc[0][l] += x0.x * wv.x + x0.y * wv.y + x0.z * wv.z + x0.w * wv.w;
            acc[1][l] += x1.x * wv.x + x1.y * wv.y + x1.z * wv.z + x1.w * wv.w;
        }
    }

#pragma unroll
    for (int r = 0; r < 2; r++)
#pragma unroll
        for (int l = 0; l < LL; l++) {
            float v = acc[r][l];
            v += __shfl_xor_sync(0xffffffffu, v, 16);
            v += __shfl_xor_sync(0xffffffffu, v, 8);
            v += __shfl_xor_sync(0xffffffffu, v, 4);
            v += __shfl_xor_sync(0xffffffffu, v, 2);
            v += __shfl_xor_sync(0xffffffffu, v, 1);
            acc[r][l] = v;
        }

#pragma unroll
    for (int r = 0; r < 2; r++) {
        if (lane == r) {
#pragma unroll
            for (int l = 0; l < LL; l++)
                g_em[(size_t)(row0 + r) * LL + l] = acc[r][l] + shb[l];
        }
    }
}

// ---------------------------------------------------------------------------
// Kernel 2: chunked scan + fused numerator partials. Grid (NC, BB), 128 thr.
// Warps 0-2: 9x9 transfer matrix of a 64-step chunk (3 rows per warp).
// Warp 3: gold-path numerator partial + mask count for the chunk.
// exp2 of emissions computed on the fly while staging into smem.
// ---------------------------------------------------------------------------
__global__ __launch_bounds__(128) void crf_chunk_kernel(
    const int* __restrict__ mask, const int* __restrict__ labels,
    const float* __restrict__ trans, const float* __restrict__ start_t)
{
    __shared__ float sem[CLEN * LL];
    __shared__ int smk[CLEN];
    __shared__ int slb[CLEN];

    int c = blockIdx.x;
    int b = blockIdx.y;
    int tid = threadIdx.x;
    int warp = tid >> 5, lane = tid & 31;
    int t0 = c * CLEN;

    for (int i = tid; i < CLEN * LL; i += 128)
        sem[i] = ex2f(g_em[((size_t)b * SS + t0) * LL + i] * L2E);
    if (tid < CLEN) smk[tid] = mask[b * SS + t0 + tid];
    else if (tid < 2 * CLEN) slb[tid - CLEN] = labels[b * SS + t0 + tid - CLEN];
    __syncthreads();

    if (warp < 3) {
        int lr = lane / 9, j = lane - lr * 9;   // lanes 27-31: harmless garbage
        int row = warp * 3 + lr;

        float et[LL];
#pragma unroll
        for (int i = 0; i < LL; i++)
            et[i] = ex2f(trans[i * LL + j] * L2E);

        int base = lr * 9;
        float a = (row == j) ? 1.f : 0.f;
        float rs = 0.f;

        int s0 = (c == 0) ? 1 : 0;
#pragma unroll 8
        for (int s = s0; s < CLEN; s++) {
            float em = sem[s * LL + j];
            int   m  = smk[s];
            float v0 = 0.f, v1 = 0.f, v2 = 0.f;
#pragma unroll
            for (int i = 0; i < 9; i += 3) {
                v0 += __shfl_sync(0xffffffffu, a, base + i)     * et[i];
                v1 += __shfl_sync(0xffffffffu, a, base + i + 1) * et[i + 1];
                v2 += __shfl_sync(0xffffffffu, a, base + i + 2) * et[i + 2];
            }
            float v = (v0 + v1 + v2) * em;
            a = m ? v : a;

            if ((s & 7) == 7) {
                float mx = -CUDART_INF_F;
#pragma unroll
                for (int i = 0; i < 9; i++)
                    mx = fmaxf(mx, __shfl_sync(0xffffffffu, a, base + i));
                a *= (1.f / mx);
                rs += lg2f(mx);
            }
        }

        if (lane < 27) {
            g_P[((size_t)b * NC + c) * 81 + row * 9 + j] = a;
            if (j == 0)
                g_rs[((size_t)b * NC + c) * LL + row] = rs;
        }
    } else {
        // numerator partial: 2 steps per lane
        float acc = 0.f;
        int mc = 0;
#pragma unroll
        for (int ss = lane; ss < CLEN; ss += 32) {
            int l = slb[ss];
            int m = smk[ss];
            mc += m;
            float em = g_em[((size_t)b * SS + t0 + ss) * LL + l];
            if (c == 0 && ss == 0) {
                acc += start_t[l] + em;          // unmasked first term
            } else {
                int lprev = (ss == 0) ? labels[b * SS + t0 - 1] : slb[ss - 1];
                acc += m ? (__ldg(&trans[lprev * LL + l]) + em) : 0.f;
            }
        }
#pragma unroll
        for (int off = 16; off > 0; off >>= 1) {
            acc += __shfl_xor_sync(0xffffffffu, acc, off);
            mc  += __shfl_xor_sync(0xffffffffu, mc,  off);
        }
        if (lane == 0) {
            g_np[b * NC + c] = acc;
            g_mc[b * NC + c] = mc;
        }
    }
}

// ---------------------------------------------------------------------------
// Kernel 3: combine — one block (1 warp) per batch. Stage chunk data into
// smem coalesced, fold from smem, then the LAST block to finish performs the
// deterministic 64-way final sum (threadfence-reduction pattern).
// ---------------------------------------------------------------------------
__global__ __launch_bounds__(32) void crf_combine_kernel(
    const float* __restrict__ start_t, const float* __restrict__ end_t,
    const int* __restrict__ labels, float* __restrict__ out)
{
    __shared__ float sP[NC * 81];
    __shared__ float srs[NC * LL];
    __shared__ float salpha[LL];
    __shared__ float sv[LL];

    int b = blockIdx.x;
    int lane = threadIdx.x;

    // coalesced stage (full-warp MLP)
    for (int i = lane; i < NC * 81; i += 32)
        sP[i] = g_P[(size_t)b * NC * 81 + i];
    for (int i = lane; i < NC * LL; i += 32)
        srs[i] = g_rs[(size_t)b * NC * LL + i];
    if (lane < LL)
        salpha[lane] = ex2f((start_t[lane] + g_em[(size_t)b * SS * LL + lane]) * L2E);
    __syncwarp();

    float sc = 0.f;
#pragma unroll
    for (int c = 0; c < NC; c++) {
        float rmax = srs[c * LL];
#pragma unroll
        for (int i = 1; i < LL; i++) rmax = fmaxf(rmax, srs[c * LL + i]);

        float ai[LL];
#pragma unroll
        for (int i = 0; i < LL; i++)
            ai[i] = salpha[i] * ex2f(srs[c * LL + i] - rmax);

        if (lane < LL) {
            float v = 0.f;
#pragma unroll
            for (int i = 0; i < LL; i++)
                v += ai[i] * sP[c * 81 + i * 9 + lane];
            sv[lane] = v;
        }
        __syncwarp();

        float mx = sv[0];
#pragma unroll
        for (int j = 1; j < LL; j++) mx = fmaxf(mx, sv[j]);

        if (lane < LL) salpha[lane] = sv[lane] * (1.f / mx);
        sc += rmax + lg2f(mx);
        __syncwarp();
    }

    // denom (every lane computes the same value; lane 0 writes)
    float ssum = 0.f;
#pragma unroll
    for (int j = 0; j < LL; j++)
        ssum += salpha[j] * ex2f(end_t[j] * L2E);
    float denom = (sc + lg2f(ssum)) * LN2;

    int isLast = 0;
    if (lane == 0) {
        float num = 0.f;
        int mt = 0;
#pragma unroll
        for (int c = 0; c < NC; c++) {
            num += g_np[b * NC + c];
            mt  += g_mc[b * NC + c];
        }
        num += end_t[labels[b * SS + mt - 1]];
        g_loss[b] = denom - num;
        __threadfence();
        int v = atomicAdd(&g_done, 1);
        isLast = (v == BB - 1);
    }
    isLast = __shfl_sync(0xffffffffu, isLast, 0);

    if (isLast) {
        __threadfence();     // acquire: make all g_loss writes visible
        float v = g_loss[lane] + g_loss[lane + 32];
        v += __shfl_xor_sync(0xffffffffu, v, 16);
        v += __shfl_xor_sync(0xffffffffu, v, 8);
        v += __shfl_xor_sync(0xffffffffu, v, 4);
        v += __shfl_xor_sync(0xffffffffu, v, 2);
        v += __shfl_xor_sync(0xffffffffu, v, 1);
        if (lane == 0) {
            out[0] = v;
            g_done = 0;      // reset for next graph replay
        }
    }
}

// ---------------------------------------------------------------------------
extern "C" void kernel_launch(void* const* d_in, const int* in_sizes, int n_in,
                              void* d_out, int out_size)
{
    const float* hs      = (const float*)d_in[0];
    const int*   mask    = (const int*)  d_in[1];
    const int*   labels  = (const int*)  d_in[2];
    const float* W       = (const float*)d_in[3];
    const float* bias    = (const float*)d_in[4];
    const float* start_t = (const float*)d_in[5];
    const float* end_t   = (const float*)d_in[6];
    const float* trans   = (const float*)d_in[7];
    float* out = (float*)d_out;

    emis_kernel<<<EGRID, 512>>>(hs, W, bias);
    crf_chunk_kernel<<<dim3(NC, BB), 128>>>(mask, labels, trans, start_t);
    crf_combine_kernel<<<BB, 32>>>(start_t, end_t, labels, out);
}